// round 14
// baseline (speedup 1.0000x reference)
#include <cuda_runtime.h>
#include <cuda_fp16.h>
#include <math.h>
#include <stdint.h>

// ---------------------------------------------------------------------------
// GroupedQueryAttention: b=1, s=2048, D_MODEL=1024, 16 heads, d_k=64, 4 groups
// Round 14: flash inner loops get depth-2 ldsm->mma software pipelining
// (hide LDS latency behind 4 mmas). Everything else unchanged from round 13.
// ---------------------------------------------------------------------------

#define SEQ    2048
#define DMODEL 1024
#define NHEADS 16
#define NGRP   4
#define DK     64
#define DKV    256
#define LQKV   1536
#define NCHUNK 48          // per head: 16 direct (qt<16) + 32 partial (qt>=16)

__device__ float  g_theta[512];
__device__ __half g_Xr [SEQ * DMODEL];
__device__ __half g_W  [LQKV * DMODEL];
__device__ __half g_Wo [DMODEL * DMODEL];
__device__ __half g_QKV[SEQ * LQKV];          // Q (pre-scaled) | K
__device__ __half g_Vt [DKV * SEQ];           // V transposed: [dim][token]
__device__ __half g_O  [SEQ * DMODEL];
__device__ __half g_Oph[32 * NHEADS * 64 * 64];  // fp16 partial O (qt>=16)
__device__ float  g_Lp [32 * NHEADS * 64];       // fp32 partial l

#define ONES2 0x3C003C00u                      // half2(1.0, 1.0)

__device__ __forceinline__ uint32_t packh2(float a, float b) {
    __half2 h = __floats2half2_rn(a, b);
    return *(uint32_t*)&h;
}

__device__ __forceinline__ uint32_t h2exp2(uint32_t x) {
    uint32_t r;
    asm("ex2.approx.f16x2 %0, %1;" : "=r"(r) : "r"(x));
    return r;
}

__device__ __forceinline__ void mma16(float* c, const uint32_t* a,
                                      uint32_t b0, uint32_t b1) {
    asm volatile(
        "mma.sync.aligned.m16n8k16.row.col.f32.f16.f16.f32 "
        "{%0,%1,%2,%3}, {%4,%5,%6,%7}, {%8,%9}, {%0,%1,%2,%3};\n"
        : "+f"(c[0]), "+f"(c[1]), "+f"(c[2]), "+f"(c[3])
        : "r"(a[0]), "r"(a[1]), "r"(a[2]), "r"(a[3]), "r"(b0), "r"(b1));
}

__device__ __forceinline__ void ldsm4(uint32_t& r0, uint32_t& r1,
                                      uint32_t& r2, uint32_t& r3,
                                      const __half* p) {
    uint32_t a = (uint32_t)__cvta_generic_to_shared(p);
    asm volatile("ldmatrix.sync.aligned.m8n8.x4.shared.b16 {%0,%1,%2,%3}, [%4];"
                 : "=r"(r0), "=r"(r1), "=r"(r2), "=r"(r3) : "r"(a));
}

__device__ __forceinline__ void cpa16(void* smem, const void* g) {
    uint32_t s = (uint32_t)__cvta_generic_to_shared(smem);
    asm volatile("cp.async.cg.shared.global [%0], [%1], 16;\n" :: "r"(s), "l"(g));
}
__device__ __forceinline__ void cpa_commit() {
    asm volatile("cp.async.commit_group;\n");
}
__device__ __forceinline__ void cpa_wait0() {
    asm volatile("cp.async.wait_group 0;\n");
}
__device__ __forceinline__ void cpa_wait1() {
    asm volatile("cp.async.wait_group 1;\n");
}
__device__ __forceinline__ void cpa_wait2() {
    asm volatile("cp.async.wait_group 2;\n");
}

// ---------------------------------------------------------------------------
// Prep: theta table, concat W_{q,k,v} -> half, W_o -> half.
// ---------------------------------------------------------------------------
__global__ void prep_kernel(const float* __restrict__ Wq, const float* __restrict__ Wk,
                            const float* __restrict__ Wv, const float* __restrict__ Wo,
                            __half* __restrict__ W, __half* __restrict__ Woh,
                            float* __restrict__ theta) {
    int bx = blockIdx.x;
    if (bx < LQKV) {
        const float* src = (bx < 1024) ? Wq + (size_t)bx * DMODEL
                         : (bx < 1280) ? Wk + (size_t)(bx - 1024) * DMODEL
                                       : Wv + (size_t)(bx - 1280) * DMODEL;
        float4 v = ((const float4*)src)[threadIdx.x];
        __half2* d = (__half2*)(W + (size_t)bx * DMODEL) + threadIdx.x * 2;
        d[0] = __floats2half2_rn(v.x, v.y);
        d[1] = __floats2half2_rn(v.z, v.w);
    } else if (bx < LQKV + DMODEL) {
        int row = bx - LQKV;
        float4 v = ((const float4*)(Wo + (size_t)row * DMODEL))[threadIdx.x];
        __half2* d = (__half2*)(Woh + (size_t)row * DMODEL) + threadIdx.x * 2;
        d[0] = __floats2half2_rn(v.x, v.y);
        d[1] = __floats2half2_rn(v.z, v.w);
    } else {
        int i = (bx - LQKV - DMODEL) * 256 + threadIdx.x;
        if (i < 512) theta[i] = (float)pow(10000.0, -(double)i / 512.0);
    }
}

// ---------------------------------------------------------------------------
// RoPE -> half output.
// ---------------------------------------------------------------------------
__global__ void rope_kernel(const float* __restrict__ X, __half* __restrict__ Xr,
                            const float* __restrict__ theta) {
    int t = blockIdx.x;
    int i = threadIdx.x;            // 0..511
    float ang = (float)t * theta[i];
    float s, c;
    __sincosf(ang, &s, &c);
    float xe = X[t * DMODEL + 2 * i];
    float xo = X[t * DMODEL + 2 * i + 1];
    Xr[t * DMODEL + i]       = __float2half_rn(xe * c - xo * s);
    Xr[t * DMODEL + 512 + i] = __float2half_rn(xe * s + xo * c);
}

// ---------------------------------------------------------------------------
// fp16 GEMM (NT), 4-stage cp.async. MODE 0: qkv (Q pre-scaled, V -> Vt
// transposed). MODE 1: fp32 out. (unchanged)
// ---------------------------------------------------------------------------
#define GS2 72
template<int NTN, int MODE>
__global__ __launch_bounds__(256) void hgemm(
    const __half* __restrict__ Abase, const __half* __restrict__ Bbase,
    void* __restrict__ Cout, __half* __restrict__ Vt)
{
    extern __shared__ __align__(16) char smraw[];
    __half* sm = (__half*)smraw;
    const int ABUF = 128 * GS2;
    const int BBUF = 32 * NTN * GS2;
    const int STRIDE = ABUF + BBUF;

    const int tid  = threadIdx.x;
    const int lane = tid & 31;
    const int wid  = tid >> 5;
    const int gq   = lane >> 2;
    const int tg   = lane & 3;
    const int wm   = (wid >> 2) * 64;
    const int wn   = (wid & 3) * 8 * NTN;
    const __half* A = Abase + (size_t)blockIdx.y * 128 * DMODEL;
    const __half* B = Bbase + (size_t)blockIdx.x * (32 * NTN) * DMODEL;

    float acc[4][NTN][4];
    #pragma unroll
    for (int mt = 0; mt < 4; mt++)
        #pragma unroll
        for (int nt = 0; nt < NTN; nt++)
            #pragma unroll
            for (int i = 0; i < 4; i++) acc[mt][nt][i] = 0.f;

    const int NK = DMODEL / 64;   // 16 chunks

    auto issue = [&](int t) {
        __half* Ad = sm + (t & 3) * STRIDE;
        __half* Bd = Ad + ABUF;
        const int k0 = t * 64;
        #pragma unroll
        for (int i = 0; i < 4; i++) {
            int idx = tid + 256 * i; int r = idx >> 3, c = idx & 7;
            cpa16(Ad + r * GS2 + c * 8, A + (size_t)r * DMODEL + k0 + c * 8);
        }
        #pragma unroll
        for (int i = 0; i < NTN; i++) {
            int idx = tid + 256 * i; int r = idx >> 3, c = idx & 7;
            cpa16(Bd + r * GS2 + c * 8, B + (size_t)r * DMODEL + k0 + c * 8);
        }
    };

    issue(0); cpa_commit();
    issue(1); cpa_commit();
    issue(2); cpa_commit();

    for (int t = 0; t < NK; t++) {
        cpa_wait2();
        __syncthreads();
        if (t + 3 < NK) issue(t + 3);
        cpa_commit();
        const __half* Asb = sm + (t & 3) * STRIDE;
        const __half* Bsb = Asb + ABUF;

        #pragma unroll
        for (int ks = 0; ks < 4; ks++) {
            uint32_t af[4][4];
            #pragma unroll
            for (int mt = 0; mt < 4; mt++) {
                const __half* p = Asb + (wm + mt * 16 + gq) * GS2 + ks * 16 + 2 * tg;
                af[mt][0] = *(const uint32_t*)p;
                af[mt][1] = *(const uint32_t*)(p + 8 * GS2);
                af[mt][2] = *(const uint32_t*)(p + 8);
                af[mt][3] = *(const uint32_t*)(p + 8 * GS2 + 8);
            }
            uint32_t bf[NTN][2];
            #pragma unroll
            for (int nt = 0; nt < NTN; nt++) {
                const __half* p = Bsb + (wn + nt * 8 + gq) * GS2 + ks * 16 + 2 * tg;
                bf[nt][0] = *(const uint32_t*)p;
                bf[nt][1] = *(const uint32_t*)(p + 8);
            }
            #pragma unroll
            for (int mt = 0; mt < 4; mt++)
                #pragma unroll
                for (int nt = 0; nt < NTN; nt++)
                    mma16(acc[mt][nt], af[mt], bf[nt][0], bf[nt][1]);
        }
    }

    const float QSC = 0.125f * 1.44269504088896340736f;  // folded into Q
    const int tile_m = blockIdx.y * 128;
    const int tile_n = blockIdx.x * (32 * NTN);
    #pragma unroll
    for (int mt = 0; mt < 4; mt++) {
        #pragma unroll
        for (int nt = 0; nt < NTN; nt++) {
            const int row = tile_m + wm + mt * 16 + gq;
            const int col = tile_n + wn + nt * 8 + 2 * tg;
            if (MODE == 0) {
                __half* Ch = (__half*)Cout;
                float a0 = acc[mt][nt][0], a1 = acc[mt][nt][1];
                float a2 = acc[mt][nt][2], a3 = acc[mt][nt][3];
                if (col < DMODEL) { a0 *= QSC; a1 *= QSC; a2 *= QSC; a3 *= QSC; }
                uint32_t h0 = packh2(a0, a1);
                uint32_t h1 = packh2(a2, a3);
                if (col < DMODEL + DKV) {          // Q | K region
                    *(uint32_t*)&Ch[(size_t)row * LQKV + col] = h0;
                    *(uint32_t*)&Ch[(size_t)(row + 8) * LQKV + col] = h1;
                } else {                            // V -> transposed Vt[dim][token]
                    const int d = col - (DMODEL + DKV);
                    __half2 p0 = *(__half2*)&h0;
                    __half2 p1 = *(__half2*)&h1;
                    Vt[(size_t)d * SEQ + row]           = __low2half(p0);
                    Vt[(size_t)(d + 1) * SEQ + row]     = __high2half(p0);
                    Vt[(size_t)d * SEQ + row + 8]       = __low2half(p1);
                    Vt[(size_t)(d + 1) * SEQ + row + 8] = __high2half(p1);
                }
            } else {
                float* Cf = (float*)Cout;
                *(float2*)&Cf[(size_t)row * DMODEL + col] =
                    make_float2(acc[mt][nt][0], acc[mt][nt][1]);
                *(float2*)&Cf[(size_t)(row + 8) * DMODEL + col] =
                    make_float2(acc[mt][nt][2], acc[mt][nt][3]);
            }
        }
    }
}

// ---------------------------------------------------------------------------
// Flash split-KV, <=16-tile chunks, depth-2 pipelined ldsm->mma.
// grid (48, 16), cx = 47 - bx:
//   cx < 16:  qt = cx, full range -> normalize + write Oh directly
//   cx >= 16: i = cx-16, qt = 16+i/2, c = i%2 -> fp16 partials + fp32 l.
// ---------------------------------------------------------------------------
#define HS 72
__global__ __launch_bounds__(128) void flash_part(
    const __half* __restrict__ QKVh, const __half* __restrict__ Vt,
    __half* __restrict__ Oh, __half* __restrict__ Oph, float* __restrict__ Lp)
{
    extern __shared__ __align__(16) char fsraw[];
    __half* Ksm = (__half*)fsraw;             // [3][64*HS]
    __half* Vsm = Ksm + 3 * 64 * HS;          // [3][64*HS]

    const int cx = 47 - blockIdx.x;           // big chunks launch first
    const int h  = blockIdx.y;
    int qt, t0, t1, pslot;
    if (cx < 16) {
        qt = cx; t0 = 0; t1 = qt + 1; pslot = -1;
    } else {
        const int i = cx - 16;
        qt = 16 + (i >> 1);
        const int c = i & 1;
        t0 = c * 16;
        t1 = c ? (qt + 1) : 16;
        pslot = h * 32 + i;
    }

    const int gkv = h >> 2;
    const int tid  = threadIdx.x;
    const int lane = tid & 31;
    const int wid  = tid >> 5;      // 0..3
    const int gq   = lane >> 2;
    const int tg   = lane & 3;
    const int row0 = qt * 64;

    const int lrow  = ((lane >> 4) & 1) * 8 + (lane & 7);
    const int lkoff = ((lane >> 3) & 1) * 8;

    const __half* Qb = QKVh + h * DK;
    const __half* Kb = QKVh + DMODEL + gkv * DK;
    const __half* Vb = Vt + (size_t)gkv * DK * SEQ;

    auto issueKV = [&](int t) {
        __half* Kd = Ksm + (t % 3) * 64 * HS;
        __half* Vd = Vsm + (t % 3) * 64 * HS;
        const size_t to = (size_t)t * 64;
        #pragma unroll
        for (int i = 0; i < 4; i++) {
            int idx = tid + 128 * i; int r = idx >> 3, cc = idx & 7;
            cpa16(Kd + r * HS + cc * 8, Kb + (to + r) * LQKV + cc * 8);
            cpa16(Vd + r * HS + cc * 8, Vb + (size_t)r * SEQ + to + cc * 8);
        }
        cpa_commit();
    };

    issueKV(t0);
    if (t0 + 1 < t1) issueKV(t0 + 1);

    // Q fragments straight from global (per-warp rows; pre-scaled)
    uint32_t qf[4][4];
    {
        const __half* q0 = Qb + (size_t)(row0 + wid * 16 + gq) * LQKV + 2 * tg;
        const __half* q1 = q0 + (size_t)8 * LQKV;
        #pragma unroll
        for (int ks = 0; ks < 4; ks++) {
            qf[ks][0] = *(const uint32_t*)(q0 + ks * 16);
            qf[ks][1] = *(const uint32_t*)(q1 + ks * 16);
            qf[ks][2] = *(const uint32_t*)(q0 + ks * 16 + 8);
            qf[ks][3] = *(const uint32_t*)(q1 + ks * 16 + 8);
        }
    }

    float l_acc[4] = {0.f, 0.f, 0.f, 0.f};
    float o[8][4];
    #pragma unroll
    for (int nt = 0; nt < 8; nt++)
        #pragma unroll
        for (int cc = 0; cc < 4; cc++) o[nt][cc] = 0.f;

    for (int kt = t0; kt < t1; kt++) {
        if (kt < t1 - 1) cpa_wait1(); else cpa_wait0();
        __syncthreads();
        if (kt + 2 < t1) issueKV(kt + 2);
        const __half* kb = Ksm + (kt % 3) * 64 * HS;
        const __half* vb = Vsm + (kt % 3) * 64 * HS;

        // ---- S = Q K^T : flattened (ks,np), depth-2 ldsm pipeline ----
        float s[8][4];
        #pragma unroll
        for (int nt = 0; nt < 8; nt++)
            #pragma unroll
            for (int cc = 0; cc < 4; cc++) s[nt][cc] = 0.f;

        {
            auto kaddr = [&](int i) {
                return kb + ((i & 3) * 16 + lrow) * HS + (i >> 2) * 16 + lkoff;
            };
            uint32_t fr[3][4];
            ldsm4(fr[0][0], fr[0][1], fr[0][2], fr[0][3], kaddr(0));
            ldsm4(fr[1][0], fr[1][1], fr[1][2], fr[1][3], kaddr(1));
            #pragma unroll
            for (int i = 0; i < 16; i++) {
                if (i + 2 < 16) {
                    uint32_t* f = fr[(i + 2) % 3];
                    ldsm4(f[0], f[1], f[2], f[3], kaddr(i + 2));
                }
                const int ks = i >> 2, np = i & 3;
                const uint32_t* f = fr[i % 3];
                mma16(s[2 * np],     qf[ks], f[0], f[1]);
                mma16(s[2 * np + 1], qf[ks], f[2], f[3]);
            }
        }

        // ---- causal mask (diagonal tile only) ----
        if (kt == qt) {
            const int rg = row0 + wid * 16 + gq;
            #pragma unroll
            for (int nt = 0; nt < 8; nt++) {
                int cg = kt * 64 + nt * 8 + 2 * tg;
                if (cg     > rg)     s[nt][0] = -1e30f;
                if (cg + 1 > rg)     s[nt][1] = -1e30f;
                if (cg     > rg + 8) s[nt][2] = -1e30f;
                if (cg + 1 > rg + 8) s[nt][3] = -1e30f;
            }
        }

        // ---- P = exp2(S) straight into A-fragment registers ----
        uint32_t ph[8][2];
        #pragma unroll
        for (int nt = 0; nt < 8; nt++) {
            ph[nt][0] = h2exp2(packh2(s[nt][0], s[nt][1]));
            ph[nt][1] = h2exp2(packh2(s[nt][2], s[nt][3]));
        }

        // ---- O += P V ; l += P 1 : flattened, depth-2 pipeline ----
        {
            auto vaddr = [&](int i) {
                return vb + ((i & 3) * 16 + lrow) * HS + (i >> 2) * 16 + lkoff;
            };
            uint32_t fr[3][4];
            ldsm4(fr[0][0], fr[0][1], fr[0][2], fr[0][3], vaddr(0));
            ldsm4(fr[1][0], fr[1][1], fr[1][2], fr[1][3], vaddr(1));
            #pragma unroll
            for (int i = 0; i < 16; i++) {
                if (i + 2 < 16) {
                    uint32_t* f = fr[(i + 2) % 3];
                    ldsm4(f[0], f[1], f[2], f[3], vaddr(i + 2));
                }
                const int ks = i >> 2, np = i & 3;
                uint32_t pa[4] = { ph[2 * ks][0], ph[2 * ks][1],
                                   ph[2 * ks + 1][0], ph[2 * ks + 1][1] };
                const uint32_t* f = fr[i % 3];
                mma16(o[2 * np],     pa, f[0], f[1]);
                mma16(o[2 * np + 1], pa, f[2], f[3]);
                if (np == 3) mma16(l_acc, pa, ONES2, ONES2);
            }
        }
    }

    const int r0l = wid * 16 + gq;
    if (pslot < 0) {
        // ---- direct: normalize and write Oh ----
        const float inv0 = 1.f / l_acc[0];
        const float inv1 = 1.f / l_acc[2];
        #pragma unroll
        for (int nt = 0; nt < 8; nt++) {
            const int row = row0 + r0l;
            const int col = h * DK + nt * 8 + 2 * tg;
            *(uint32_t*)&Oh[(size_t)row * DMODEL + col] =
                packh2(o[nt][0] * inv0, o[nt][1] * inv0);
            *(uint32_t*)&Oh[(size_t)(row + 8) * DMODEL + col] =
                packh2(o[nt][2] * inv1, o[nt][3] * inv1);
        }
    } else {
        // ---- partial: fp16 O + fp32 l ----
        __half* po = Oph + (size_t)pslot * 4096;
        #pragma unroll
        for (int nt = 0; nt < 8; nt++) {
            const int col = nt * 8 + 2 * tg;
            *(uint32_t*)&po[r0l * 64 + col]       = packh2(o[nt][0], o[nt][1]);
            *(uint32_t*)&po[(r0l + 8) * 64 + col] = packh2(o[nt][2], o[nt][3]);
        }
        if (tg == 0) {
            Lp[pslot * 64 + r0l]     = l_acc[0];
            Lp[pslot * 64 + r0l + 8] = l_acc[2];
        }
    }
}

// ---------------------------------------------------------------------------
// Combine (qt >= 16 only): sum the 2 fp16 partials in fp32, normalize, emit.
// ---------------------------------------------------------------------------
__global__ __launch_bounds__(128) void flash_combine(
    const __half* __restrict__ Oph, const float* __restrict__ Lp,
    __half* __restrict__ Oh)
{
    const int q = blockIdx.x, h = blockIdx.y;
    const int s0 = h * 32 + q * 2;
    const int s1 = s0 + 1;
    const int tid = threadIdx.x;
    const int row = tid >> 1;
    const int d0  = (tid & 1) * 32;

    const float l = Lp[s0 * 64 + row] + Lp[s1 * 64 + row];
    const float inv = 1.f / l;

    const __half2* p0 = (const __half2*)(Oph + (size_t)s0 * 4096 + row * 64 + d0);
    const __half2* p1 = (const __half2*)(Oph + (size_t)s1 * 4096 + row * 64 + d0);
    uint32_t* dst = (uint32_t*)&Oh[(size_t)((16 + q) * 64 + row) * DMODEL + h * DK + d0];
    #pragma unroll
    for (int j = 0; j < 16; j++) {
        float2 a = __half22float2(p0[j]);
        float2 b = __half22float2(p1[j]);
        dst[j] = packh2((a.x + b.x) * inv, (a.y + b.y) * inv);
    }
}

// ---------------------------------------------------------------------------
extern "C" void kernel_launch(void* const* d_in, const int* in_sizes, int n_in,
                              void* d_out, int out_size)
{
    const float* X  = (const float*)d_in[0];
    const float* Wq = (const float*)d_in[1];
    const float* Wk = (const float*)d_in[2];
    const float* Wv = (const float*)d_in[3];
    const float* Wo = (const float*)d_in[4];
    float* out = (float*)d_out;

    __half *Xr, *W, *Woh, *QKV, *Vt, *Oh, *Oph;
    float *theta, *Lp;
    cudaGetSymbolAddress((void**)&Xr,    g_Xr);
    cudaGetSymbolAddress((void**)&W,     g_W);
    cudaGetSymbolAddress((void**)&Woh,   g_Wo);
    cudaGetSymbolAddress((void**)&QKV,   g_QKV);
    cudaGetSymbolAddress((void**)&Vt,    g_Vt);
    cudaGetSymbolAddress((void**)&Oh,    g_O);
    cudaGetSymbolAddress((void**)&Oph,   g_Oph);
    cudaGetSymbolAddress((void**)&theta, g_theta);
    cudaGetSymbolAddress((void**)&Lp,    g_Lp);

    const int qkv_smem   = 4 * (128 + 192) * GS2 * 2;   // 184320
    const int o_smem     = 4 * (128 + 128) * GS2 * 2;   // 147456
    const int flash_smem = 3 * 2 * 64 * HS * 2;         // 55296

    static bool attr_done = false;
    if (!attr_done) {
        cudaFuncSetAttribute(hgemm<6, 0>,
            cudaFuncAttributeMaxDynamicSharedMemorySize, qkv_smem);
        cudaFuncSetAttribute(hgemm<4, 1>,
            cudaFuncAttributeMaxDynamicSharedMemorySize, o_smem);
        cudaFuncSetAttribute(flash_part,
            cudaFuncAttributeMaxDynamicSharedMemorySize, flash_smem);
        attr_done = true;
    }

    prep_kernel<<<LQKV + DMODEL + 2, 256>>>(Wq, Wk, Wv, Wo, W, Woh, theta);
    rope_kernel<<<SEQ, 512>>>(X, Xr, theta);

    // QKV: [2048,1536] = Xr x W^T; Q pre-scaled; V slab transposed into Vt
    hgemm<6, 0><<<dim3(8, 16), 256, qkv_smem>>>(Xr, W, QKV, Vt);

    flash_part<<<dim3(NCHUNK, NHEADS), 128, flash_smem>>>(QKV, Vt, Oh, Oph, Lp);
    flash_combine<<<dim3(16, NHEADS), 128>>>(Oph, Lp, Oh);

    // out: [2048,1024] = attnO x Wo^T (fp32 result)
    hgemm<4, 1><<<dim3(8, 16), 256, o_smem>>>(Oh, Woh, out, nullptr);
}

// round 15
// speedup vs baseline: 1.0280x; 1.0280x over previous
#include <cuda_runtime.h>
#include <cuda_fp16.h>
#include <math.h>
#include <stdint.h>

// ---------------------------------------------------------------------------
// GroupedQueryAttention: b=1, s=2048, D_MODEL=1024, 16 heads, d_k=64, 4 groups
// Round 15: V via ldmatrix.trans (no Vt transpose scatter), combine kernel
// replaced by in-flash flag-based merge (c0 short chunk writes partial+flag,
// c1 full chunk merges). prep zeros flags. GEMM core unchanged.
// ---------------------------------------------------------------------------

#define SEQ    2048
#define DMODEL 1024
#define NHEADS 16
#define NGRP   4
#define DK     64
#define DKV    256
#define LQKV   1536
#define NCHUNK 48          // per head: 16 direct (qt<16) + 32 paired (qt>=16)

__device__ float  g_theta[512];
__device__ __half g_Xr [SEQ * DMODEL];
__device__ __half g_W  [LQKV * DMODEL];
__device__ __half g_Wo [DMODEL * DMODEL];
__device__ __half g_QKV[SEQ * LQKV];             // Q (pre-scaled) | K | V
__device__ __half g_O  [SEQ * DMODEL];
__device__ __half g_Oph[16 * NHEADS * 64 * 64];  // fp16 partial O (c0 chunks)
__device__ float  g_Lp [16 * NHEADS * 64];       // fp32 partial l
__device__ int    g_flag[16 * NHEADS];           // c0 -> c1 handoff flags

#define ONES2 0x3C003C00u                         // half2(1.0, 1.0)

__device__ __forceinline__ uint32_t packh2(float a, float b) {
    __half2 h = __floats2half2_rn(a, b);
    return *(uint32_t*)&h;
}

__device__ __forceinline__ uint32_t h2exp2(uint32_t x) {
    uint32_t r;
    asm("ex2.approx.f16x2 %0, %1;" : "=r"(r) : "r"(x));
    return r;
}

__device__ __forceinline__ void mma16(float* c, const uint32_t* a,
                                      uint32_t b0, uint32_t b1) {
    asm volatile(
        "mma.sync.aligned.m16n8k16.row.col.f32.f16.f16.f32 "
        "{%0,%1,%2,%3}, {%4,%5,%6,%7}, {%8,%9}, {%0,%1,%2,%3};\n"
        : "+f"(c[0]), "+f"(c[1]), "+f"(c[2]), "+f"(c[3])
        : "r"(a[0]), "r"(a[1]), "r"(a[2]), "r"(a[3]), "r"(b0), "r"(b1));
}

__device__ __forceinline__ void ldsm4(uint32_t& r0, uint32_t& r1,
                                      uint32_t& r2, uint32_t& r3,
                                      const __half* p) {
    uint32_t a = (uint32_t)__cvta_generic_to_shared(p);
    asm volatile("ldmatrix.sync.aligned.m8n8.x4.shared.b16 {%0,%1,%2,%3}, [%4];"
                 : "=r"(r0), "=r"(r1), "=r"(r2), "=r"(r3) : "r"(a));
}

// transposed variant: loads [k][n]-stored tiles as B fragments
__device__ __forceinline__ void ldsm4t(uint32_t& r0, uint32_t& r1,
                                       uint32_t& r2, uint32_t& r3,
                                       const __half* p) {
    uint32_t a = (uint32_t)__cvta_generic_to_shared(p);
    asm volatile("ldmatrix.sync.aligned.m8n8.x4.trans.shared.b16 {%0,%1,%2,%3}, [%4];"
                 : "=r"(r0), "=r"(r1), "=r"(r2), "=r"(r3) : "r"(a));
}

__device__ __forceinline__ void cpa16(void* smem, const void* g) {
    uint32_t s = (uint32_t)__cvta_generic_to_shared(smem);
    asm volatile("cp.async.cg.shared.global [%0], [%1], 16;\n" :: "r"(s), "l"(g));
}
__device__ __forceinline__ void cpa_commit() {
    asm volatile("cp.async.commit_group;\n");
}
__device__ __forceinline__ void cpa_wait0() {
    asm volatile("cp.async.wait_group 0;\n");
}
__device__ __forceinline__ void cpa_wait1() {
    asm volatile("cp.async.wait_group 1;\n");
}
__device__ __forceinline__ void cpa_wait2() {
    asm volatile("cp.async.wait_group 2;\n");
}

// ---------------------------------------------------------------------------
// Prep: theta table, concat W_{q,k,v} -> half, W_o -> half, zero flags.
// ---------------------------------------------------------------------------
__global__ void prep_kernel(const float* __restrict__ Wq, const float* __restrict__ Wk,
                            const float* __restrict__ Wv, const float* __restrict__ Wo,
                            __half* __restrict__ W, __half* __restrict__ Woh,
                            float* __restrict__ theta, int* __restrict__ flag) {
    int bx = blockIdx.x;
    if (bx < LQKV) {
        const float* src = (bx < 1024) ? Wq + (size_t)bx * DMODEL
                         : (bx < 1280) ? Wk + (size_t)(bx - 1024) * DMODEL
                                       : Wv + (size_t)(bx - 1280) * DMODEL;
        float4 v = ((const float4*)src)[threadIdx.x];
        __half2* d = (__half2*)(W + (size_t)bx * DMODEL) + threadIdx.x * 2;
        d[0] = __floats2half2_rn(v.x, v.y);
        d[1] = __floats2half2_rn(v.z, v.w);
    } else if (bx < LQKV + DMODEL) {
        int row = bx - LQKV;
        float4 v = ((const float4*)(Wo + (size_t)row * DMODEL))[threadIdx.x];
        __half2* d = (__half2*)(Woh + (size_t)row * DMODEL) + threadIdx.x * 2;
        d[0] = __floats2half2_rn(v.x, v.y);
        d[1] = __floats2half2_rn(v.z, v.w);
    } else if (bx < LQKV + DMODEL + 2) {
        int i = (bx - LQKV - DMODEL) * 256 + threadIdx.x;
        if (i < 512) theta[i] = (float)pow(10000.0, -(double)i / 512.0);
    } else {
        flag[threadIdx.x] = 0;     // 256 handoff flags
    }
}

// ---------------------------------------------------------------------------
// RoPE -> half output.
// ---------------------------------------------------------------------------
__global__ void rope_kernel(const float* __restrict__ X, __half* __restrict__ Xr,
                            const float* __restrict__ theta) {
    int t = blockIdx.x;
    int i = threadIdx.x;            // 0..511
    float ang = (float)t * theta[i];
    float s, c;
    __sincosf(ang, &s, &c);
    float xe = X[t * DMODEL + 2 * i];
    float xo = X[t * DMODEL + 2 * i + 1];
    Xr[t * DMODEL + i]       = __float2half_rn(xe * c - xo * s);
    Xr[t * DMODEL + 512 + i] = __float2half_rn(xe * s + xo * c);
}

// ---------------------------------------------------------------------------
// fp16 GEMM (NT), 4-stage cp.async. MODE 0: qkv -> half out, Q pre-scaled
// (V stored plainly now; no transpose scatter). MODE 1: fp32 out.
// ---------------------------------------------------------------------------
#define GS2 72
template<int NTN, int MODE>
__global__ __launch_bounds__(256) void hgemm(
    const __half* __restrict__ Abase, const __half* __restrict__ Bbase,
    void* __restrict__ Cout)
{
    extern __shared__ __align__(16) char smraw[];
    __half* sm = (__half*)smraw;
    const int ABUF = 128 * GS2;
    const int BBUF = 32 * NTN * GS2;
    const int STRIDE = ABUF + BBUF;

    const int tid  = threadIdx.x;
    const int lane = tid & 31;
    const int wid  = tid >> 5;
    const int gq   = lane >> 2;
    const int tg   = lane & 3;
    const int wm   = (wid >> 2) * 64;
    const int wn   = (wid & 3) * 8 * NTN;
    const __half* A = Abase + (size_t)blockIdx.y * 128 * DMODEL;
    const __half* B = Bbase + (size_t)blockIdx.x * (32 * NTN) * DMODEL;

    float acc[4][NTN][4];
    #pragma unroll
    for (int mt = 0; mt < 4; mt++)
        #pragma unroll
        for (int nt = 0; nt < NTN; nt++)
            #pragma unroll
            for (int i = 0; i < 4; i++) acc[mt][nt][i] = 0.f;

    const int NK = DMODEL / 64;   // 16 chunks

    auto issue = [&](int t) {
        __half* Ad = sm + (t & 3) * STRIDE;
        __half* Bd = Ad + ABUF;
        const int k0 = t * 64;
        #pragma unroll
        for (int i = 0; i < 4; i++) {
            int idx = tid + 256 * i; int r = idx >> 3, c = idx & 7;
            cpa16(Ad + r * GS2 + c * 8, A + (size_t)r * DMODEL + k0 + c * 8);
        }
        #pragma unroll
        for (int i = 0; i < NTN; i++) {
            int idx = tid + 256 * i; int r = idx >> 3, c = idx & 7;
            cpa16(Bd + r * GS2 + c * 8, B + (size_t)r * DMODEL + k0 + c * 8);
        }
    };

    issue(0); cpa_commit();
    issue(1); cpa_commit();
    issue(2); cpa_commit();

    for (int t = 0; t < NK; t++) {
        cpa_wait2();
        __syncthreads();
        if (t + 3 < NK) issue(t + 3);
        cpa_commit();
        const __half* Asb = sm + (t & 3) * STRIDE;
        const __half* Bsb = Asb + ABUF;

        #pragma unroll
        for (int ks = 0; ks < 4; ks++) {
            uint32_t af[4][4];
            #pragma unroll
            for (int mt = 0; mt < 4; mt++) {
                const __half* p = Asb + (wm + mt * 16 + gq) * GS2 + ks * 16 + 2 * tg;
                af[mt][0] = *(const uint32_t*)p;
                af[mt][1] = *(const uint32_t*)(p + 8 * GS2);
                af[mt][2] = *(const uint32_t*)(p + 8);
                af[mt][3] = *(const uint32_t*)(p + 8 * GS2 + 8);
            }
            uint32_t bf[NTN][2];
            #pragma unroll
            for (int nt = 0; nt < NTN; nt++) {
                const __half* p = Bsb + (wn + nt * 8 + gq) * GS2 + ks * 16 + 2 * tg;
                bf[nt][0] = *(const uint32_t*)p;
                bf[nt][1] = *(const uint32_t*)(p + 8);
            }
            #pragma unroll
            for (int mt = 0; mt < 4; mt++)
                #pragma unroll
                for (int nt = 0; nt < NTN; nt++)
                    mma16(acc[mt][nt], af[mt], bf[nt][0], bf[nt][1]);
        }
    }

    const float QSC = 0.125f * 1.44269504088896340736f;  // folded into Q
    const int tile_m = blockIdx.y * 128;
    const int tile_n = blockIdx.x * (32 * NTN);
    #pragma unroll
    for (int mt = 0; mt < 4; mt++) {
        #pragma unroll
        for (int nt = 0; nt < NTN; nt++) {
            const int row = tile_m + wm + mt * 16 + gq;
            const int col = tile_n + wn + nt * 8 + 2 * tg;
            if (MODE == 0) {
                __half* Ch = (__half*)Cout;
                float a0 = acc[mt][nt][0], a1 = acc[mt][nt][1];
                float a2 = acc[mt][nt][2], a3 = acc[mt][nt][3];
                if (col < DMODEL) { a0 *= QSC; a1 *= QSC; a2 *= QSC; a3 *= QSC; }
                *(uint32_t*)&Ch[(size_t)row * LQKV + col] = packh2(a0, a1);
                *(uint32_t*)&Ch[(size_t)(row + 8) * LQKV + col] = packh2(a2, a3);
            } else {
                float* Cf = (float*)Cout;
                *(float2*)&Cf[(size_t)row * DMODEL + col] =
                    make_float2(acc[mt][nt][0], acc[mt][nt][1]);
                *(float2*)&Cf[(size_t)(row + 8) * DMODEL + col] =
                    make_float2(acc[mt][nt][2], acc[mt][nt][3]);
            }
        }
    }
}

// ---------------------------------------------------------------------------
// Flash split-KV. grid (48, 16), cx = 47 - bx:
//   cx < 16: qt = cx, tiles [0, qt] -> normalize + write Oh directly.
//   cx >= 16: i = cx-16, qt = 16 + i/2.
//     i odd  (launches first): c0 = remainder tiles [16, qt+1) -> writes fp16
//            partial + fp32 l + release flag.
//     i even: c1 = tiles [0,16) -> computes, polls flag, merges c0's partial
//            into fp32 accumulators, normalizes, writes Oh.
// V loaded [token][dim] and fragments fetched with ldmatrix.trans.
// ---------------------------------------------------------------------------
#define HS 72
__global__ __launch_bounds__(128) void flash_part(
    const __half* __restrict__ QKVh, __half* __restrict__ Oh,
    __half* __restrict__ Oph, float* __restrict__ Lp, int* __restrict__ flag)
{
    extern __shared__ __align__(16) char fsraw[];
    __half* Ksm = (__half*)fsraw;             // [3][64*HS]
    __half* Vsm = Ksm + 3 * 64 * HS;          // [3][64*HS]

    const int cx = 47 - blockIdx.x;           // paired chunks launch first
    const int h  = blockIdx.y;
    int qt, t0, t1;
    int role = 0;                              // 0 direct, 1 c0 (partial), 2 c1 (merge)
    if (cx < 16) {
        qt = cx; t0 = 0; t1 = qt + 1;
    } else {
        const int i = cx - 16;
        qt = 16 + (i >> 1);
        if (i & 1) { role = 1; t0 = 16; t1 = qt + 1; }   // short remainder, first
        else       { role = 2; t0 = 0;  t1 = 16; }       // full chunk, merges
    }
    const int slot = h * 16 + (qt - 16);       // valid when role != 0

    const int gkv = h >> 2;
    const int tid  = threadIdx.x;
    const int lane = tid & 31;
    const int wid  = tid >> 5;      // 0..3
    const int gq   = lane >> 2;
    const int tg   = lane & 3;
    const int row0 = qt * 64;

    // K (non-trans) lane geometry
    const int lrow  = ((lane >> 4) & 1) * 8 + (lane & 7);
    const int lkoff = ((lane >> 3) & 1) * 8;
    // V (trans) lane geometry
    const int trow  = ((lane >> 3) & 1) * 8 + (lane & 7);
    const int tdoff = ((lane >> 4) & 1) * 8;

    const __half* Qb = QKVh + h * DK;
    const __half* Kb = QKVh + DMODEL + gkv * DK;
    const __half* Vb = QKVh + DMODEL + DKV + gkv * DK;

    auto issueKV = [&](int t) {
        __half* Kd = Ksm + (t % 3) * 64 * HS;
        __half* Vd = Vsm + (t % 3) * 64 * HS;
        const size_t to = (size_t)t * 64;
        #pragma unroll
        for (int i = 0; i < 4; i++) {
            int idx = tid + 128 * i; int r = idx >> 3, cc = idx & 7;
            cpa16(Kd + r * HS + cc * 8, Kb + (to + r) * LQKV + cc * 8);
            cpa16(Vd + r * HS + cc * 8, Vb + (to + r) * LQKV + cc * 8);
        }
        cpa_commit();
    };

    issueKV(t0);
    if (t0 + 1 < t1) issueKV(t0 + 1);

    // Q fragments straight from global (per-warp rows; pre-scaled)
    uint32_t qf[4][4];
    {
        const __half* q0 = Qb + (size_t)(row0 + wid * 16 + gq) * LQKV + 2 * tg;
        const __half* q1 = q0 + (size_t)8 * LQKV;
        #pragma unroll
        for (int ks = 0; ks < 4; ks++) {
            qf[ks][0] = *(const uint32_t*)(q0 + ks * 16);
            qf[ks][1] = *(const uint32_t*)(q1 + ks * 16);
            qf[ks][2] = *(const uint32_t*)(q0 + ks * 16 + 8);
            qf[ks][3] = *(const uint32_t*)(q1 + ks * 16 + 8);
        }
    }

    float l_acc[4] = {0.f, 0.f, 0.f, 0.f};
    float o[8][4];
    #pragma unroll
    for (int nt = 0; nt < 8; nt++)
        #pragma unroll
        for (int cc = 0; cc < 4; cc++) o[nt][cc] = 0.f;

    for (int kt = t0; kt < t1; kt++) {
        if (kt < t1 - 1) cpa_wait1(); else cpa_wait0();
        __syncthreads();
        if (kt + 2 < t1) issueKV(kt + 2);
        const __half* kb = Ksm + (kt % 3) * 64 * HS;
        const __half* vb = Vsm + (kt % 3) * 64 * HS;

        // ---- S = Q K^T ----
        float s[8][4];
        #pragma unroll
        for (int nt = 0; nt < 8; nt++)
            #pragma unroll
            for (int cc = 0; cc < 4; cc++) s[nt][cc] = 0.f;

        #pragma unroll
        for (int ks = 0; ks < 4; ks++) {
            #pragma unroll
            for (int np = 0; np < 4; np++) {
                uint32_t b0, b1, b2, b3;
                ldsm4(b0, b1, b2, b3,
                      kb + (np * 16 + lrow) * HS + ks * 16 + lkoff);
                mma16(s[2 * np],     qf[ks], b0, b1);
                mma16(s[2 * np + 1], qf[ks], b2, b3);
            }
        }

        // ---- causal mask (diagonal tile only) ----
        if (kt == qt) {
            const int rg = row0 + wid * 16 + gq;
            #pragma unroll
            for (int nt = 0; nt < 8; nt++) {
                int cg = kt * 64 + nt * 8 + 2 * tg;
                if (cg     > rg)     s[nt][0] = -1e30f;
                if (cg + 1 > rg)     s[nt][1] = -1e30f;
                if (cg     > rg + 8) s[nt][2] = -1e30f;
                if (cg + 1 > rg + 8) s[nt][3] = -1e30f;
            }
        }

        // ---- P = exp2(S) into A-fragment registers ----
        uint32_t ph[8][2];
        #pragma unroll
        for (int nt = 0; nt < 8; nt++) {
            ph[nt][0] = h2exp2(packh2(s[nt][0], s[nt][1]));
            ph[nt][1] = h2exp2(packh2(s[nt][2], s[nt][3]));
        }

        // ---- O += P V (trans ldsm on [token][dim]) ; l += P 1 ----
        #pragma unroll
        for (int ks = 0; ks < 4; ks++) {
            uint32_t pa[4] = { ph[2 * ks][0], ph[2 * ks][1],
                               ph[2 * ks + 1][0], ph[2 * ks + 1][1] };
            #pragma unroll
            for (int np = 0; np < 4; np++) {
                uint32_t b0, b1, b2, b3;
                ldsm4t(b0, b1, b2, b3,
                       vb + (ks * 16 + trow) * HS + np * 16 + tdoff);
                mma16(o[2 * np],     pa, b0, b1);
                mma16(o[2 * np + 1], pa, b2, b3);
            }
            mma16(l_acc, pa, ONES2, ONES2);
        }
    }

    const int r0l = wid * 16 + gq;
    if (role == 1) {
        // ---- c0: fp16 partial + fp32 l + release flag ----
        __half* po = Oph + (size_t)slot * 4096;
        #pragma unroll
        for (int nt = 0; nt < 8; nt++) {
            const int col = nt * 8 + 2 * tg;
            *(uint32_t*)&po[r0l * 64 + col]       = packh2(o[nt][0], o[nt][1]);
            *(uint32_t*)&po[(r0l + 8) * 64 + col] = packh2(o[nt][2], o[nt][3]);
        }
        if (tg == 0) {
            Lp[slot * 64 + r0l]     = l_acc[0];
            Lp[slot * 64 + r0l + 8] = l_acc[2];
        }
        __threadfence();
        __syncthreads();
        if (tid == 0) atomicExch(&flag[slot], 1);
        return;
    }

    if (role == 2) {
        // ---- c1: wait for c0, merge its partial ----
        if (tid == 0) {
            while (atomicAdd(&flag[slot], 0) == 0) __nanosleep(100);
        }
        __syncthreads();
        __threadfence();
        const __half* po = Oph + (size_t)slot * 4096;
        l_acc[0] += Lp[slot * 64 + r0l];
        l_acc[2] += Lp[slot * 64 + r0l + 8];
        #pragma unroll
        for (int nt = 0; nt < 8; nt++) {
            const int col = nt * 8 + 2 * tg;
            float2 a = __half22float2(*(const __half2*)&po[r0l * 64 + col]);
            float2 b = __half22float2(*(const __half2*)&po[(r0l + 8) * 64 + col]);
            o[nt][0] += a.x; o[nt][1] += a.y;
            o[nt][2] += b.x; o[nt][3] += b.y;
        }
    }

    // ---- normalize and write Oh (direct and c1) ----
    const float inv0 = 1.f / l_acc[0];
    const float inv1 = 1.f / l_acc[2];
    #pragma unroll
    for (int nt = 0; nt < 8; nt++) {
        const int row = row0 + r0l;
        const int col = h * DK + nt * 8 + 2 * tg;
        *(uint32_t*)&Oh[(size_t)row * DMODEL + col] =
            packh2(o[nt][0] * inv0, o[nt][1] * inv0);
        *(uint32_t*)&Oh[(size_t)(row + 8) * DMODEL + col] =
            packh2(o[nt][2] * inv1, o[nt][3] * inv1);
    }
}

// ---------------------------------------------------------------------------
extern "C" void kernel_launch(void* const* d_in, const int* in_sizes, int n_in,
                              void* d_out, int out_size)
{
    const float* X  = (const float*)d_in[0];
    const float* Wq = (const float*)d_in[1];
    const float* Wk = (const float*)d_in[2];
    const float* Wv = (const float*)d_in[3];
    const float* Wo = (const float*)d_in[4];
    float* out = (float*)d_out;

    __half *Xr, *W, *Woh, *QKV, *Oh, *Oph;
    float *theta, *Lp;
    int *flag;
    cudaGetSymbolAddress((void**)&Xr,    g_Xr);
    cudaGetSymbolAddress((void**)&W,     g_W);
    cudaGetSymbolAddress((void**)&Woh,   g_Wo);
    cudaGetSymbolAddress((void**)&QKV,   g_QKV);
    cudaGetSymbolAddress((void**)&Oh,    g_O);
    cudaGetSymbolAddress((void**)&Oph,   g_Oph);
    cudaGetSymbolAddress((void**)&theta, g_theta);
    cudaGetSymbolAddress((void**)&Lp,    g_Lp);
    cudaGetSymbolAddress((void**)&flag,  g_flag);

    const int qkv_smem   = 4 * (128 + 192) * GS2 * 2;   // 184320
    const int o_smem     = 4 * (128 + 128) * GS2 * 2;   // 147456
    const int flash_smem = 3 * 2 * 64 * HS * 2;         // 55296

    static bool attr_done = false;
    if (!attr_done) {
        cudaFuncSetAttribute(hgemm<6, 0>,
            cudaFuncAttributeMaxDynamicSharedMemorySize, qkv_smem);
        cudaFuncSetAttribute(hgemm<4, 1>,
            cudaFuncAttributeMaxDynamicSharedMemorySize, o_smem);
        cudaFuncSetAttribute(flash_part,
            cudaFuncAttributeMaxDynamicSharedMemorySize, flash_smem);
        attr_done = true;
    }

    prep_kernel<<<LQKV + DMODEL + 3, 256>>>(Wq, Wk, Wv, Wo, W, Woh, theta, flag);
    rope_kernel<<<SEQ, 512>>>(X, Xr, theta);

    // QKV: [2048,1536] = Xr x W^T; Q pre-scaled by 1/sqrt(dk)*log2(e)
    hgemm<6, 0><<<dim3(8, 16), 256, qkv_smem>>>(Xr, W, QKV);

    flash_part<<<dim3(NCHUNK, NHEADS), 128, flash_smem>>>(QKV, Oh, Oph, Lp, flag);

    // out: [2048,1024] = attnO x Wo^T (fp32 result)
    hgemm<4, 1><<<dim3(8, 16), 256, o_smem>>>(Oh, Woh, out);
}